// round 1
// baseline (speedup 1.0000x reference)
#include <cuda_runtime.h>

#define HWD   96
#define NVOX  (96*96*96)        /* 884736 voxels per volume   */
#define NVOL  8                 /* 4 pred + 4 target volumes  */
#define NTOT  (NVOX*NVOL)       /* 7077888                    */
#define NELEM (4*NVOX)          /* elements per input tensor  */

// scratch (device globals: allocation-free per harness rules)
__device__ int            g_label[NTOT];
__device__ unsigned char  g_fg[NTOT];
__device__ double         g_focal;
__device__ int            g_counts[NVOL];

// ---------------------------------------------------------------------------
// init: fg masks, x-run chain labels, clear accumulators
// ---------------------------------------------------------------------------
__global__ void k_init(const float* __restrict__ pred,
                       const float* __restrict__ tgt)
{
    int idx = blockIdx.x * blockDim.x + threadIdx.x;
    if (idx >= NTOT) return;
    if (idx == 0) {
        g_focal = 0.0;
        #pragma unroll
        for (int v = 0; v < NVOL; ++v) g_counts[v] = 0;
    }
    int d = idx % HWD;            // D is innermost (stride-1) axis
    bool fg, fgprev = false;
    if (idx < 4*NVOX) {           // pred volumes: sigmoid(x) > 0.5  <=>  x > 0
        fg = pred[idx] > 0.0f;
        if (d > 0) fgprev = pred[idx-1] > 0.0f;
    } else {                      // target volumes: t > 0.5
        int o = idx - 4*NVOX;
        fg = tgt[o] > 0.5f;
        if (d > 0) fgprev = tgt[o-1] > 0.5f;
    }
    g_fg[idx]    = fg ? 1 : 0;
    g_label[idx] = (fg && fgprev) ? (idx - 1) : idx;
}

// ---------------------------------------------------------------------------
// focal loss partial reduction (double accumulation)
// ---------------------------------------------------------------------------
__global__ void k_focal(const float* __restrict__ pred,
                        const float* __restrict__ tgt)
{
    int i = blockIdx.x * blockDim.x + threadIdx.x;
    double v = 0.0;
    if (i < NELEM) {
        float x = pred[i];
        float t = tgt[i];
        // softplus(x) - x*t  (numerically stable)
        float sp  = fmaxf(x, 0.0f) + log1pf(expf(-fabsf(x)));
        float bce = sp - x * t;
        float p   = 1.0f / (1.0f + expf(-x));
        bool  one = t > 0.5f;
        float pt  = one ? p : 1.0f - p;
        float at  = one ? 0.25f : 0.75f;
        float om  = 1.0f - pt;
        v = (double)(at * om * om * bce);
    }
    // warp reduce
    #pragma unroll
    for (int off = 16; off > 0; off >>= 1)
        v += __shfl_down_sync(0xffffffffu, v, off);
    __shared__ double s[8];
    int lane = threadIdx.x & 31, w = threadIdx.x >> 5;
    if (lane == 0) s[w] = v;
    __syncthreads();
    if (w == 0) {
        v = (lane < (blockDim.x >> 5)) ? s[lane] : 0.0;
        #pragma unroll
        for (int off = 4; off > 0; off >>= 1)
            v += __shfl_down_sync(0xffffffffu, v, off);
        if (lane == 0) atomicAdd(&g_focal, v);
    }
}

// ---------------------------------------------------------------------------
// compress x-run chains (safe: no concurrent unions at this point)
// ---------------------------------------------------------------------------
__global__ void k_compress()
{
    int idx = blockIdx.x * blockDim.x + threadIdx.x;
    if (idx >= NTOT) return;
    int p = g_label[idx];
    if (p != idx) {
        int q = g_label[p];
        while (q != p) { p = q; q = g_label[p]; }
        g_label[idx] = p;
    }
}

// ---------------------------------------------------------------------------
// union-find merge along +W and +H (ECL-CC style hooks)
// ---------------------------------------------------------------------------
__device__ __forceinline__ int findroot(int i)
{
    int p = g_label[i];
    while (p != i) { i = p; p = g_label[i]; }
    return i;
}

__device__ __forceinline__ void unite(int a, int b)
{
    a = findroot(a);
    b = findroot(b);
    while (a != b) {
        if (a > b) { int t = a; a = b; b = t; }   // hook larger onto smaller
        int old = atomicMin(&g_label[b], a);
        if (old == b) return;                     // successful hook
        b = old;                                  // lost race: retry from old
        a = findroot(a);
        b = findroot(b);
    }
}

__global__ void k_merge()
{
    int idx = blockIdx.x * blockDim.x + threadIdx.x;
    if (idx >= NTOT) return;
    if (!g_fg[idx]) return;
    int loc = idx % NVOX;
    int w   = (loc / HWD) % HWD;
    int h   = loc / (HWD * HWD);
    if (w < HWD-1 && g_fg[idx + HWD])       unite(idx, idx + HWD);
    if (h < HWD-1 && g_fg[idx + HWD*HWD])   unite(idx, idx + HWD*HWD);
}

// ---------------------------------------------------------------------------
// count roots per volume (block fully inside one volume: NVOX % 256 == 0)
// ---------------------------------------------------------------------------
__global__ void k_count()
{
    int idx = blockIdx.x * 256 + threadIdx.x;
    int c = (g_fg[idx] && g_label[idx] == idx) ? 1 : 0;
    int wsum = __popc(__ballot_sync(0xffffffffu, c));
    __shared__ int s;
    if (threadIdx.x == 0) s = 0;
    __syncthreads();
    if ((threadIdx.x & 31) == 0) atomicAdd(&s, wsum);
    __syncthreads();
    if (threadIdx.x == 0 && s > 0)
        atomicAdd(&g_counts[blockIdx.x / (NVOX/256)], s);
}

// ---------------------------------------------------------------------------
// final combine
// ---------------------------------------------------------------------------
__global__ void k_final(float* __restrict__ out)
{
    // volumes in reshape(B*C): v = b*C + c with B=2, C=2
    float c0 = (float)g_counts[0], c1 = (float)g_counts[1];
    float c2 = (float)g_counts[2], c3 = (float)g_counts[3];
    float t0 = (float)g_counts[4], t1 = (float)g_counts[5];
    float t2 = (float)g_counts[6], t3 = (float)g_counts[7];
    float ccp0 = 0.5f*(c0 + c2), ccp1 = 0.5f*(c1 + c3);   // mean over batch
    float cct0 = 0.5f*(t0 + t2), cct1 = 0.5f*(t1 + t3);
    float topo = 0.5f*(fabsf(ccp0 - cct0) + fabsf(ccp1 - cct1)); // mean over C
    float focal = (float)(g_focal / (double)NELEM);
    out[0] = focal + 0.1f * topo;
}

// ---------------------------------------------------------------------------
extern "C" void kernel_launch(void* const* d_in, const int* in_sizes, int n_in,
                              void* d_out, int out_size)
{
    const float* pred = (const float*)d_in[0];
    const float* tgt  = (const float*)d_in[1];
    float*       out  = (float*)d_out;

    const int T = 256;
    k_init    <<<(NTOT  + T-1)/T, T>>>(pred, tgt);
    k_focal   <<<(NELEM + T-1)/T, T>>>(pred, tgt);
    k_compress<<<(NTOT  + T-1)/T, T>>>();
    k_merge   <<<(NTOT  + T-1)/T, T>>>();
    k_count   <<<NTOT/T, T>>>();
    k_final   <<<1, 1>>>(out);
}